// round 5
// baseline (speedup 1.0000x reference)
#include <cuda_runtime.h>
#include <cstdint>

#define B_  32
#define C_  256
#define H_  64
#define W_  64
#define HW_ 4096
#define EPS 1e-5f

// ---------------- scratch (device globals: no allocations allowed) ----------
__device__ float g_edge[(size_t)B_ * C_ * HW_];   // relu(bn(dwconv(x)))
__device__ float g_t1 [(size_t)B_ * C_ * HW_];    // bn1(fusion conv)
__device__ float g_t2 [(size_t)B_ * C_ * HW_];    // deform dwconv output
__device__ float g_avg[B_ * C_];
__device__ float g_att[B_ * C_];

// ---------------- 1) per-(b,c) spatial mean --------------------------------
__global__ __launch_bounds__(256) void mean_kernel(const float* __restrict__ x) {
    int plane = blockIdx.x;                       // b*C + c
    const float* p = x + (size_t)plane * HW_;
    float s = 0.f;
    for (int i = threadIdx.x; i < HW_; i += 256) s += p[i];
    #pragma unroll
    for (int o = 16; o; o >>= 1) s += __shfl_xor_sync(0xffffffffu, s, o);
    __shared__ float ws[8];
    if ((threadIdx.x & 31) == 0) ws[threadIdx.x >> 5] = s;
    __syncthreads();
    if (threadIdx.x == 0) {
        float t = 0.f;
        #pragma unroll
        for (int i = 0; i < 8; i++) t += ws[i];
        g_avg[plane] = t * (1.0f / HW_);
    }
}

// ---------------- 2) SE MLP: att = sigmoid(relu(avg@fc1^T)@fc2^T) ----------
__global__ __launch_bounds__(512) void se_kernel(const float* __restrict__ fc1_w,
                                                 const float* __restrict__ fc2_w) {
    __shared__ float sa[B_ * C_];     // 32 KB
    __shared__ float shh[B_ * 16];
    int tid = threadIdx.x;            // 512 threads
    for (int i = tid; i < B_ * C_; i += 512) sa[i] = g_avg[i];
    __syncthreads();
    {
        int b = tid >> 4, j = tid & 15;
        float s = 0.f;
        #pragma unroll 8
        for (int c = 0; c < C_; c++) s += sa[b * C_ + c] * fc1_w[j * C_ + c];
        shh[b * 16 + j] = fmaxf(s, 0.f);
    }
    __syncthreads();
    for (int idx = tid; idx < B_ * C_; idx += 512) {
        int b = idx >> 8, o = idx & 255;
        float s = 0.f;
        #pragma unroll
        for (int j = 0; j < 16; j++) s += shh[b * 16 + j] * fc2_w[o * 16 + j];
        g_att[idx] = 1.0f / (1.0f + expf(-s));
    }
}

// ---------------- 3/5) depthwise 3x3 (optionally +BN+ReLU) -----------------
__global__ __launch_bounds__(256) void dwconv_kernel(const float* __restrict__ src,
                                                     const float* __restrict__ w9,
                                                     float* __restrict__ dst,
                                                     const float* __restrict__ gma,
                                                     const float* __restrict__ bta,
                                                     const float* __restrict__ mn,
                                                     const float* __restrict__ vr,
                                                     int do_bnrelu) {
    __shared__ float sh[66][67];
    int plane = blockIdx.x;                       // b*C + c
    int c = plane & (C_ - 1);
    const float* sp = src + (size_t)plane * HW_;
    int tid = threadIdx.x;
    for (int idx = tid; idx < 66 * 66; idx += 256) {
        int r = idx / 66, cc = idx - r * 66;
        int yy = r - 1, xx = cc - 1;
        float v = 0.f;
        if (yy >= 0 && yy < H_ && xx >= 0 && xx < W_) v = sp[yy * W_ + xx];
        sh[r][cc] = v;
    }
    float w[9];
    #pragma unroll
    for (int i = 0; i < 9; i++) w[i] = w9[c * 9 + i];
    float inv = 1.f, add = 0.f;
    if (do_bnrelu) { inv = gma[c] * rsqrtf(vr[c] + EPS); add = bta[c] - mn[c] * inv; }
    __syncthreads();
    float* dp = dst + (size_t)plane * HW_;
    #pragma unroll
    for (int i = 0; i < 16; i++) {
        int p = tid + i * 256;
        int row = p >> 6, col = p & 63;
        float s = 0.f;
        #pragma unroll
        for (int dy = 0; dy < 3; dy++)
            #pragma unroll
            for (int dx = 0; dx < 3; dx++)
                s += w[dy * 3 + dx] * sh[row + dy][col + dx];
        if (do_bnrelu) s = fmaxf(s * inv + add, 0.f);
        dp[p] = s;
    }
}

// ---------------- big-tile SGEMM: 128x128 tile, 8x8 per thread --------------
// GEMM1: KTOT=512, B rows = [x*att ; edge], epilogue = BN1(+bias) -> g_t1
// GEMM2: KTOT=256, B rows = g_t2, epilogue = BN2(+bias) * x -> out
template<int KTOT, bool IS_G1>
__global__ __launch_bounds__(256, 2) void gemm_kernel(
    const float* __restrict__ bsrc,   // G1: x ; G2: g_t2
    const float* __restrict__ aw,     // weights [256, KTOT] row-major
    const float* __restrict__ bias,
    const float* __restrict__ gma, const float* __restrict__ bta,
    const float* __restrict__ mn,  const float* __restrict__ vr,
    const float* __restrict__ xg,     // G2: x (gate) ; G1: unused
    float* __restrict__ dst)
{
    __shared__ float As[2][16][128];
    __shared__ float Bs[2][16][128];

    const int b  = blockIdx.z;
    const int o0 = blockIdx.y * 128;
    const int p0 = blockIdx.x * 128;
    const int tid = threadIdx.x;
    const int tm = tid >> 4;          // 0..15 (row group)
    const int tn = tid & 15;          // 0..15 (col group)

    const float* xb = bsrc   + (size_t)b * C_ * HW_;
    const float* eb = g_edge + (size_t)b * C_ * HW_;

    // A load mapping: row am (0..127), k-quad ak (0 or 8), 2 float4 along K
    const int am = tid & 127;
    const int ak = (tid >> 7) * 8;
    // B load mapping: rows 2*bk2, 2*bk2+1 ; cols bn..bn+3
    const int bk2 = tid >> 5;         // 0..7
    const int bn  = (tid & 31) * 4;   // 0..124

    float acc[8][8];
    #pragma unroll
    for (int i = 0; i < 8; i++)
        #pragma unroll
        for (int j = 0; j < 8; j++) acc[i][j] = 0.f;

    float4 a0, a1, b0, b1;

    // ---- load helpers (inlined manually) ----
    #define LOAD_TILE(K0)                                                        \
    {                                                                            \
        const float* ap = aw + (size_t)(o0 + am) * KTOT + (K0) + ak;             \
        a0 = *(const float4*)ap;                                                 \
        a1 = *(const float4*)(ap + 4);                                           \
        int kB = (K0) + bk2 * 2;                                                 \
        if (IS_G1) {                                                             \
            if ((K0) < C_) {                                                     \
                float s0 = g_att[b * C_ + kB];                                   \
                float s1 = g_att[b * C_ + kB + 1];                               \
                b0 = *(const float4*)(xb + (size_t)kB * HW_ + p0 + bn);          \
                b1 = *(const float4*)(xb + (size_t)(kB + 1) * HW_ + p0 + bn);    \
                b0.x *= s0; b0.y *= s0; b0.z *= s0; b0.w *= s0;                  \
                b1.x *= s1; b1.y *= s1; b1.z *= s1; b1.w *= s1;                  \
            } else {                                                             \
                b0 = *(const float4*)(eb + (size_t)(kB - C_) * HW_ + p0 + bn);   \
                b1 = *(const float4*)(eb + (size_t)(kB + 1 - C_) * HW_ + p0 + bn);\
            }                                                                    \
        } else {                                                                 \
            b0 = *(const float4*)(xb + (size_t)kB * HW_ + p0 + bn);              \
            b1 = *(const float4*)(xb + (size_t)(kB + 1) * HW_ + p0 + bn);        \
        }                                                                        \
    }

    #define STORE_TILE(BUF)                                                      \
    {                                                                            \
        As[BUF][ak + 0][am] = a0.x; As[BUF][ak + 1][am] = a0.y;                  \
        As[BUF][ak + 2][am] = a0.z; As[BUF][ak + 3][am] = a0.w;                  \
        As[BUF][ak + 4][am] = a1.x; As[BUF][ak + 5][am] = a1.y;                  \
        As[BUF][ak + 6][am] = a1.z; As[BUF][ak + 7][am] = a1.w;                  \
        *(float4*)&Bs[BUF][bk2 * 2][bn]     = b0;                                \
        *(float4*)&Bs[BUF][bk2 * 2 + 1][bn] = b1;                                \
    }

    LOAD_TILE(0);
    STORE_TILE(0);
    __syncthreads();

    const int NT = KTOT / 16;
    for (int t = 0; t < NT; t++) {
        int cur = t & 1;
        if (t + 1 < NT) LOAD_TILE((t + 1) * 16);
        #pragma unroll
        for (int kk = 0; kk < 16; kk++) {
            float4 fa0 = *(const float4*)&As[cur][kk][tm * 8];
            float4 fa1 = *(const float4*)&As[cur][kk][tm * 8 + 4];
            float4 fb0 = *(const float4*)&Bs[cur][kk][tn * 4];
            float4 fb1 = *(const float4*)&Bs[cur][kk][64 + tn * 4];
            float ra[8] = {fa0.x, fa0.y, fa0.z, fa0.w, fa1.x, fa1.y, fa1.z, fa1.w};
            float rb[8] = {fb0.x, fb0.y, fb0.z, fb0.w, fb1.x, fb1.y, fb1.z, fb1.w};
            #pragma unroll
            for (int i = 0; i < 8; i++)
                #pragma unroll
                for (int j = 0; j < 8; j++)
                    acc[i][j] += ra[i] * rb[j];
        }
        if (t + 1 < NT) STORE_TILE(cur ^ 1);
        __syncthreads();
    }
    #undef LOAD_TILE
    #undef STORE_TILE

    // ---- epilogue ----
    const size_t base = (size_t)b * C_ * HW_;
    #pragma unroll
    for (int i = 0; i < 8; i++) {
        int o = o0 + tm * 8 + i;
        float inv = gma[o] * rsqrtf(vr[o] + EPS);
        float add = bta[o] - mn[o] * inv + bias[o] * inv;
        size_t off0 = base + (size_t)o * HW_ + p0 + tn * 4;
        size_t off1 = off0 + 64;
        float4 r0, r1;
        r0.x = acc[i][0] * inv + add; r0.y = acc[i][1] * inv + add;
        r0.z = acc[i][2] * inv + add; r0.w = acc[i][3] * inv + add;
        r1.x = acc[i][4] * inv + add; r1.y = acc[i][5] * inv + add;
        r1.z = acc[i][6] * inv + add; r1.w = acc[i][7] * inv + add;
        if (!IS_G1) {
            float4 x0 = *(const float4*)(xg + off0);
            float4 x1 = *(const float4*)(xg + off1);
            r0.x *= x0.x; r0.y *= x0.y; r0.z *= x0.z; r0.w *= x0.w;
            r1.x *= x1.x; r1.y *= x1.y; r1.z *= x1.z; r1.w *= x1.w;
        }
        *(float4*)(dst + off0) = r0;
        *(float4*)(dst + off1) = r1;
    }
}

// ---------------- launch ----------------------------------------------------
extern "C" void kernel_launch(void* const* d_in, const int* in_sizes, int n_in,
                              void* d_out, int out_size) {
    const float* x          = (const float*)d_in[0];
    const float* edge_w     = (const float*)d_in[1];
    const float* edge_gamma = (const float*)d_in[2];
    const float* edge_beta  = (const float*)d_in[3];
    const float* edge_mean  = (const float*)d_in[4];
    const float* edge_var   = (const float*)d_in[5];
    const float* fc1_w      = (const float*)d_in[6];
    const float* fc2_w      = (const float*)d_in[7];
    const float* fusion_w   = (const float*)d_in[8];
    const float* fusion_b   = (const float*)d_in[9];
    const float* bn1_gamma  = (const float*)d_in[10];
    const float* bn1_beta   = (const float*)d_in[11];
    const float* bn1_mean   = (const float*)d_in[12];
    const float* bn1_var    = (const float*)d_in[13];
    const float* deform_w   = (const float*)d_in[14];
    const float* balance_w  = (const float*)d_in[15];
    const float* balance_b  = (const float*)d_in[16];
    const float* bn2_gamma  = (const float*)d_in[17];
    const float* bn2_beta   = (const float*)d_in[18];
    const float* bn2_mean   = (const float*)d_in[19];
    const float* bn2_var    = (const float*)d_in[20];
    float* out = (float*)d_out;

    float *pe = nullptr, *pt1 = nullptr, *pt2 = nullptr;
    cudaGetSymbolAddress((void**)&pe,  g_edge);
    cudaGetSymbolAddress((void**)&pt1, g_t1);
    cudaGetSymbolAddress((void**)&pt2, g_t2);

    const int nplanes = B_ * C_;

    // 1) spatial mean for SE
    mean_kernel<<<nplanes, 256>>>(x);
    // 2) SE MLP -> g_att
    se_kernel<<<1, 512>>>(fc1_w, fc2_w);
    // 3) edge branch: dwconv + BN + ReLU -> g_edge
    dwconv_kernel<<<nplanes, 256>>>(x, edge_w, pe,
                                    edge_gamma, edge_beta, edge_mean, edge_var, 1);
    // 4) fusion 1x1 conv (K=512, SE scaling folded in) + bias + BN1 -> g_t1
    dim3 grid(HW_ / 128, C_ / 128, B_);     // 32 x 2 x 32
    gemm_kernel<512, true><<<grid, 256>>>(x, fusion_w, fusion_b,
                                          bn1_gamma, bn1_beta, bn1_mean, bn1_var,
                                          nullptr, pt1);
    // 5) deform (zero-offset) dwconv -> g_t2
    dwconv_kernel<<<nplanes, 256>>>(pt1, deform_w, pt2,
                                    nullptr, nullptr, nullptr, nullptr, 0);
    // 6) balance 1x1 conv + bias + BN2, gated by x -> out
    gemm_kernel<256, false><<<grid, 256>>>(pt2, balance_w, balance_b,
                                           bn2_gamma, bn2_beta, bn2_mean, bn2_var,
                                           x, out);
}

// round 7
// speedup vs baseline: 1.7167x; 1.7167x over previous
#include <cuda_runtime.h>
#include <cstdint>

#define B_  32
#define C_  256
#define H_  64
#define W_  64
#define HW_ 4096
#define EPS 1e-5f

// ---------------- scratch (device globals: no allocations allowed) ----------
__device__ float g_edge[(size_t)B_ * C_ * HW_];   // relu(bn(dwconv(x)))
__device__ float g_t1 [(size_t)B_ * C_ * HW_];    // bn1(fusion conv)
__device__ float g_t2 [(size_t)B_ * C_ * HW_];    // deform dwconv output
__device__ float g_avg[B_ * C_];
__device__ float g_att[B_ * C_];

// ---------------- 1) per-(b,c) spatial mean --------------------------------
__global__ __launch_bounds__(256) void mean_kernel(const float* __restrict__ x) {
    int plane = blockIdx.x;
    const float* p = x + (size_t)plane * HW_;
    float s = 0.f;
    for (int i = threadIdx.x; i < HW_; i += 256) s += p[i];
    #pragma unroll
    for (int o = 16; o; o >>= 1) s += __shfl_xor_sync(0xffffffffu, s, o);
    __shared__ float ws[8];
    if ((threadIdx.x & 31) == 0) ws[threadIdx.x >> 5] = s;
    __syncthreads();
    if (threadIdx.x == 0) {
        float t = 0.f;
        #pragma unroll
        for (int i = 0; i < 8; i++) t += ws[i];
        g_avg[plane] = t * (1.0f / HW_);
    }
}

// ---------------- 2) SE MLP -------------------------------------------------
__global__ __launch_bounds__(512) void se_kernel(const float* __restrict__ fc1_w,
                                                 const float* __restrict__ fc2_w) {
    __shared__ float sa[B_ * C_];
    __shared__ float shh[B_ * 16];
    int tid = threadIdx.x;
    for (int i = tid; i < B_ * C_; i += 512) sa[i] = g_avg[i];
    __syncthreads();
    {
        int b = tid >> 4, j = tid & 15;
        float s = 0.f;
        #pragma unroll 8
        for (int c = 0; c < C_; c++) s += sa[b * C_ + c] * fc1_w[j * C_ + c];
        shh[b * 16 + j] = fmaxf(s, 0.f);
    }
    __syncthreads();
    for (int idx = tid; idx < B_ * C_; idx += 512) {
        int b = idx >> 8, o = idx & 255;
        float s = 0.f;
        #pragma unroll
        for (int j = 0; j < 16; j++) s += shh[b * 16 + j] * fc2_w[o * 16 + j];
        g_att[idx] = 1.0f / (1.0f + expf(-s));
    }
}

// ---------------- 3/5) depthwise 3x3 (optionally +BN+ReLU) -----------------
__global__ __launch_bounds__(256) void dwconv_kernel(const float* __restrict__ src,
                                                     const float* __restrict__ w9,
                                                     float* __restrict__ dst,
                                                     const float* __restrict__ gma,
                                                     const float* __restrict__ bta,
                                                     const float* __restrict__ mn,
                                                     const float* __restrict__ vr,
                                                     int do_bnrelu) {
    __shared__ float sh[66][67];
    int plane = blockIdx.x;
    int c = plane & (C_ - 1);
    const float* sp = src + (size_t)plane * HW_;
    int tid = threadIdx.x;
    for (int idx = tid; idx < 66 * 66; idx += 256) {
        int r = idx / 66, cc = idx - r * 66;
        int yy = r - 1, xx = cc - 1;
        float v = 0.f;
        if (yy >= 0 && yy < H_ && xx >= 0 && xx < W_) v = sp[yy * W_ + xx];
        sh[r][cc] = v;
    }
    float w[9];
    #pragma unroll
    for (int i = 0; i < 9; i++) w[i] = w9[c * 9 + i];
    float inv = 1.f, add = 0.f;
    if (do_bnrelu) { inv = gma[c] * rsqrtf(vr[c] + EPS); add = bta[c] - mn[c] * inv; }
    __syncthreads();
    float* dp = dst + (size_t)plane * HW_;
    #pragma unroll
    for (int i = 0; i < 16; i++) {
        int p = tid + i * 256;
        int row = p >> 6, col = p & 63;
        float s = 0.f;
        #pragma unroll
        for (int dy = 0; dy < 3; dy++)
            #pragma unroll
            for (int dx = 0; dx < 3; dx++)
                s += w[dy * 3 + dx] * sh[row + dy][col + dx];
        if (do_bnrelu) s = fmaxf(s * inv + add, 0.f);
        dp[p] = s;
    }
}

// =================== tf32 mma.sync GEMM =====================================
__device__ __forceinline__ uint32_t f2tf32(float x) {
    uint32_t r;
    asm("cvt.rna.tf32.f32 %0, %1;" : "=r"(r) : "f"(x));
    return r;
}

__device__ __forceinline__ void mma_tf32_16x8x8(
    float& d0, float& d1, float& d2, float& d3,
    uint32_t a0, uint32_t a1, uint32_t a2, uint32_t a3,
    uint32_t b0, uint32_t b1) {
    asm volatile(
        "mma.sync.aligned.m16n8k8.row.col.f32.tf32.tf32.f32 "
        "{%0,%1,%2,%3}, {%4,%5,%6,%7}, {%8,%9}, {%0,%1,%2,%3};"
        : "+f"(d0), "+f"(d1), "+f"(d2), "+f"(d3)
        : "r"(a0), "r"(a1), "r"(a2), "r"(a3), "r"(b0), "r"(b1));
}

// Block tile: M=128 channels, N=128 pixels, K chunk 16; 8 warps (2M x 4N),
// warp tile 64x32 -> 4x4 m16n8k8 mmas per k8.
// GEMM1: KTOT=512, B rows = [x*att ; edge], epi = BN1+bias -> g_t1
// GEMM2: KTOT=256, B rows = g_t2,           epi = (BN2+bias)*x -> out
template<int KTOT, bool IS_G1>
__global__ __launch_bounds__(256, 2) void tgemm_kernel(
    const float* __restrict__ act,
    const float* __restrict__ wgt,
    const float* __restrict__ bias,
    const float* __restrict__ gma, const float* __restrict__ bta,
    const float* __restrict__ mnn, const float* __restrict__ vr,
    const float* __restrict__ xg,
    float* __restrict__ dst)
{
    __shared__ float As[2][128][20];    // [m][k] pad 20
    __shared__ float Bs[2][16][136];    // [k][n] pad 136

    const int tid = threadIdx.x;
    const int wid = tid >> 5, lane = tid & 31;
    const int g = lane >> 2, tig = lane & 3;
    const int b  = blockIdx.z;
    const int o0 = blockIdx.y * 128;
    const int p0 = blockIdx.x * 128;
    const int warpM = (wid & 1) * 64;
    const int warpN = (wid >> 1) * 32;

    const float* actb = act    + (size_t)b * C_ * HW_;
    const float* edgb = g_edge + (size_t)b * C_ * HW_;
    const float* attb = g_att  + b * C_;

    // global->reg staging mappings
    const int a_m = tid >> 1;            // 0..127
    const int a_k = (tid & 1) * 8;       // 0 or 8
    const int b_k = tid >> 4;            // 0..15
    const int b_n = (tid & 15) * 8;      // 0..120

    float acc[4][4][4];
    #pragma unroll
    for (int i = 0; i < 4; i++)
        #pragma unroll
        for (int j = 0; j < 4; j++)
            #pragma unroll
            for (int q = 0; q < 4; q++) acc[i][j][q] = 0.f;

    float4 ra0, ra1, rb0, rb1;

    #define LOAD_CHUNK(K0)                                                       \
    {                                                                            \
        const float* ap = wgt + (size_t)(o0 + a_m) * KTOT + (K0) + a_k;          \
        ra0 = *(const float4*)ap;                                                \
        ra1 = *(const float4*)(ap + 4);                                          \
        const int kg = (K0) + b_k;                                               \
        if (IS_G1) {                                                             \
            if (kg < C_) {                                                       \
                const float* bp = actb + (size_t)kg * HW_ + p0 + b_n;            \
                float s = attb[kg];                                              \
                rb0 = *(const float4*)bp;                                        \
                rb1 = *(const float4*)(bp + 4);                                  \
                rb0.x *= s; rb0.y *= s; rb0.z *= s; rb0.w *= s;                  \
                rb1.x *= s; rb1.y *= s; rb1.z *= s; rb1.w *= s;                  \
            } else {                                                             \
                const float* bp = edgb + (size_t)(kg - C_) * HW_ + p0 + b_n;     \
                rb0 = *(const float4*)bp;                                        \
                rb1 = *(const float4*)(bp + 4);                                  \
            }                                                                    \
        } else {                                                                 \
            const float* bp = actb + (size_t)kg * HW_ + p0 + b_n;                \
            rb0 = *(const float4*)bp;                                            \
            rb1 = *(const float4*)(bp + 4);                                      \
        }                                                                        \
    }

    #define STORE_CHUNK(BUF)                                                     \
    {                                                                            \
        float* aw_ = &As[BUF][a_m][a_k];                                         \
        aw_[0] = __uint_as_float(f2tf32(ra0.x));                                 \
        aw_[1] = __uint_as_float(f2tf32(ra0.y));                                 \
        aw_[2] = __uint_as_float(f2tf32(ra0.z));                                 \
        aw_[3] = __uint_as_float(f2tf32(ra0.w));                                 \
        aw_[4] = __uint_as_float(f2tf32(ra1.x));                                 \
        aw_[5] = __uint_as_float(f2tf32(ra1.y));                                 \
        aw_[6] = __uint_as_float(f2tf32(ra1.z));                                 \
        aw_[7] = __uint_as_float(f2tf32(ra1.w));                                 \
        float* bw_ = &Bs[BUF][b_k][b_n];                                         \
        bw_[0] = __uint_as_float(f2tf32(rb0.x));                                 \
        bw_[1] = __uint_as_float(f2tf32(rb0.y));                                 \
        bw_[2] = __uint_as_float(f2tf32(rb0.z));                                 \
        bw_[3] = __uint_as_float(f2tf32(rb0.w));                                 \
        bw_[4] = __uint_as_float(f2tf32(rb1.x));                                 \
        bw_[5] = __uint_as_float(f2tf32(rb1.y));                                 \
        bw_[6] = __uint_as_float(f2tf32(rb1.z));                                 \
        bw_[7] = __uint_as_float(f2tf32(rb1.w));                                 \
    }

    LOAD_CHUNK(0);
    STORE_CHUNK(0);
    __syncthreads();

    const int NT = KTOT / 16;
    for (int t = 0; t < NT; t++) {
        const int cur = t & 1;
        if (t + 1 < NT) LOAD_CHUNK((t + 1) * 16);

        #pragma unroll
        for (int kb = 0; kb < 16; kb += 8) {
            uint32_t af[4][4], bf[4][2];
            #pragma unroll
            for (int mt = 0; mt < 4; mt++) {
                const int m = warpM + mt * 16;
                af[mt][0] = __float_as_uint(As[cur][m + g    ][kb + tig]);
                af[mt][1] = __float_as_uint(As[cur][m + g + 8][kb + tig]);
                af[mt][2] = __float_as_uint(As[cur][m + g    ][kb + tig + 4]);
                af[mt][3] = __float_as_uint(As[cur][m + g + 8][kb + tig + 4]);
            }
            #pragma unroll
            for (int nt = 0; nt < 4; nt++) {
                const int n = warpN + nt * 8;
                bf[nt][0] = __float_as_uint(Bs[cur][kb + tig    ][n + g]);
                bf[nt][1] = __float_as_uint(Bs[cur][kb + tig + 4][n + g]);
            }
            #pragma unroll
            for (int mt = 0; mt < 4; mt++)
                #pragma unroll
                for (int nt = 0; nt < 4; nt++)
                    mma_tf32_16x8x8(acc[mt][nt][0], acc[mt][nt][1],
                                    acc[mt][nt][2], acc[mt][nt][3],
                                    af[mt][0], af[mt][1], af[mt][2], af[mt][3],
                                    bf[nt][0], bf[nt][1]);
        }
        if (t + 1 < NT) STORE_CHUNK(cur ^ 1);
        __syncthreads();
    }
    #undef LOAD_CHUNK
    #undef STORE_CHUNK

    // ---- epilogue: BN(+bias)(+gate) and store ----
    const size_t bb = (size_t)b * C_ * HW_;
    #pragma unroll
    for (int mt = 0; mt < 4; mt++) {
        const int olo = o0 + warpM + mt * 16 + g;
        const int ohi = olo + 8;
        const float invlo = gma[olo] * rsqrtf(vr[olo] + EPS);
        const float addlo = bta[olo] - mnn[olo] * invlo + bias[olo] * invlo;
        const float invhi = gma[ohi] * rsqrtf(vr[ohi] + EPS);
        const float addhi = bta[ohi] - mnn[ohi] * invhi + bias[ohi] * invhi;
        #pragma unroll
        for (int nt = 0; nt < 4; nt++) {
            const int n = p0 + warpN + nt * 8 + 2 * tig;
            const size_t lo = bb + (size_t)olo * HW_ + n;
            const size_t hi = bb + (size_t)ohi * HW_ + n;
            float2 vlo, vhi;
            vlo.x = acc[mt][nt][0] * invlo + addlo;
            vlo.y = acc[mt][nt][1] * invlo + addlo;
            vhi.x = acc[mt][nt][2] * invhi + addhi;
            vhi.y = acc[mt][nt][3] * invhi + addhi;
            if (!IS_G1) {
                float2 xlo = *(const float2*)(xg + lo);
                float2 xhi = *(const float2*)(xg + hi);
                vlo.x *= xlo.x; vlo.y *= xlo.y;
                vhi.x *= xhi.x; vhi.y *= xhi.y;
            }
            *(float2*)(dst + lo) = vlo;
            *(float2*)(dst + hi) = vhi;
        }
    }
}

// ---------------- launch ----------------------------------------------------
extern "C" void kernel_launch(void* const* d_in, const int* in_sizes, int n_in,
                              void* d_out, int out_size) {
    const float* x          = (const float*)d_in[0];
    const float* edge_w     = (const float*)d_in[1];
    const float* edge_gamma = (const float*)d_in[2];
    const float* edge_beta  = (const float*)d_in[3];
    const float* edge_mean  = (const float*)d_in[4];
    const float* edge_var   = (const float*)d_in[5];
    const float* fc1_w      = (const float*)d_in[6];
    const float* fc2_w      = (const float*)d_in[7];
    const float* fusion_w   = (const float*)d_in[8];
    const float* fusion_b   = (const float*)d_in[9];
    const float* bn1_gamma  = (const float*)d_in[10];
    const float* bn1_beta   = (const float*)d_in[11];
    const float* bn1_mean   = (const float*)d_in[12];
    const float* bn1_var    = (const float*)d_in[13];
    const float* deform_w   = (const float*)d_in[14];
    const float* balance_w  = (const float*)d_in[15];
    const float* balance_b  = (const float*)d_in[16];
    const float* bn2_gamma  = (const float*)d_in[17];
    const float* bn2_beta   = (const float*)d_in[18];
    const float* bn2_mean   = (const float*)d_in[19];
    const float* bn2_var    = (const float*)d_in[20];
    float* out = (float*)d_out;

    float *pe = nullptr, *pt1 = nullptr, *pt2 = nullptr;
    cudaGetSymbolAddress((void**)&pe,  g_edge);
    cudaGetSymbolAddress((void**)&pt1, g_t1);
    cudaGetSymbolAddress((void**)&pt2, g_t2);

    const int nplanes = B_ * C_;

    // 1) spatial mean for SE
    mean_kernel<<<nplanes, 256>>>(x);
    // 2) SE MLP -> g_att
    se_kernel<<<1, 512>>>(fc1_w, fc2_w);
    // 3) edge branch: dwconv + BN + ReLU -> g_edge
    dwconv_kernel<<<nplanes, 256>>>(x, edge_w, pe,
                                    edge_gamma, edge_beta, edge_mean, edge_var, 1);
    // 4) fusion 1x1 conv (tf32 mma.sync, SE folded) + bias + BN1 -> g_t1
    dim3 grid(HW_ / 128, C_ / 128, B_);   // 32 x 2 x 32
    tgemm_kernel<512, true><<<grid, 256>>>(
        x, fusion_w, fusion_b, bn1_gamma, bn1_beta, bn1_mean, bn1_var, x, pt1);
    // 5) deform (zero-offset) dwconv -> g_t2
    dwconv_kernel<<<nplanes, 256>>>(pt1, deform_w, pt2,
                                    nullptr, nullptr, nullptr, nullptr, 0);
    // 6) balance 1x1 conv + bias + BN2, gated by x -> out
    tgemm_kernel<256, false><<<grid, 256>>>(
        pt2, balance_w, balance_b, bn2_gamma, bn2_beta, bn2_mean, bn2_var, x, out);
}